// round 11
// baseline (speedup 1.0000x reference)
#include <cuda_runtime.h>

#define NN 8192
#define NE 32768
#define NB 32
#define EB 1024

// ---------------- device scratch (no allocations allowed) ----------------
__device__ int   g_is64;
__device__ int   g_src[NE], g_dst[NE];
__device__ int   g_cnt[NN];
__device__ int   g_start[NN + 1];
__device__ float g_cntf[NN];
__device__ int   g_bhist[NB * NN];
__device__ int   g_perm[NE];
__device__ float g_m[147 * NE];            // m1_aug(33)|m2_aug(49)|m3_aug(65), column-major [k][e]
__device__ float g_Wh[80 * 3200];          // Wcat tf32-hi for current conv
__device__ float g_Wl[80 * 3200];          // Wcat tf32-lo
__device__ float g_Ah[NN * 80];            // A (node features) tf32-hi for current conv
__device__ float g_Al[NN * 80];            // A tf32-lo
__device__ float g_Q[(size_t)NN * 3200];   // Q = A @ Wcat (max ~105 MB)
__device__ float g_msg[NE * 64];
__device__ float g_d3[NN * 16];
__device__ float g_gum[NN * 16];

__device__ __forceinline__ float lrelu(float v) { return v >= 0.f ? v : 0.01f * v; }

// ---------------- tf32 helpers ----------------
__device__ __forceinline__ float tf32r(float a) {
    unsigned u;
    asm("cvt.rna.tf32.f32 %0, %1;" : "=r"(u) : "f"(a));
    return __uint_as_float(u);
}

__device__ __forceinline__ void mma_tf32(float* c, const unsigned* a, const unsigned* b) {
    asm("mma.sync.aligned.m16n8k8.row.col.f32.tf32.tf32.f32 "
        "{%0,%1,%2,%3}, {%4,%5,%6,%7}, {%8,%9}, {%0,%1,%2,%3};"
        : "+f"(c[0]), "+f"(c[1]), "+f"(c[2]), "+f"(c[3])
        : "r"(a[0]), "r"(a[1]), "r"(a[2]), "r"(a[3]), "r"(b[0]), "r"(b[1]));
}

// ---------------- edge_index dtype detection + conversion ----------------
__global__ void detect_k(const void* ei) {
    if (threadIdx.x == 0) {
        const long long* p = (const long long*)ei;
        int ok = 1;
        for (int i = 0; i < 64; i++) {
            long long v = p[i];
            if (v < 0 || v >= NN) ok = 0;
        }
        g_is64 = ok;
    }
}

__global__ void convert_k(const void* ei) {
    int e = blockIdx.x * 256 + threadIdx.x;
    if (e >= NE) return;
    if (g_is64) {
        const long long* p = (const long long*)ei;
        g_src[e] = (int)p[e];
        g_dst[e] = (int)p[NE + e];
    } else {
        const int* p = (const int*)ei;
        g_src[e] = p[e];
        g_dst[e] = p[NE + e];
    }
}

// ---------------- conv1 A split: x[8192*16] -> g_Ah/g_Al ----------------
__global__ void split_x_k(const float* __restrict__ x) {
    int i = blockIdx.x * 256 + threadIdx.x;   // NN*16
    float v = x[i];
    float h = tf32r(v);
    g_Ah[i] = h;
    g_Al[i] = tf32r(v - h);
}

// ---------------- deterministic dst-CSR build ----------------
__global__ void zero_cnt_k() { g_cnt[blockIdx.x * 256 + threadIdx.x] = 0; }

__global__ void hist_k() {
    int e = blockIdx.x * 256 + threadIdx.x;
    atomicAdd(&g_cnt[g_dst[e]], 1);
}

__global__ __launch_bounds__(1024) void scan_k() {
    __shared__ int ps[1024];
    int t = threadIdx.x;
    int loc[8];
    int s = 0;
    for (int i = 0; i < 8; i++) { loc[i] = g_cnt[t * 8 + i]; s += loc[i]; }
    ps[t] = s;
    __syncthreads();
    for (int d = 1; d < 1024; d <<= 1) {
        int v = (t >= d) ? ps[t - d] : 0;
        __syncthreads();
        ps[t] += v;
        __syncthreads();
    }
    int run = (t > 0) ? ps[t - 1] : 0;
    for (int i = 0; i < 8; i++) {
        int n = t * 8 + i;
        g_start[n] = run;
        g_cntf[n]  = (float)(loc[i] > 1 ? loc[i] : 1);
        run += loc[i];
    }
    if (t == 1023) g_start[NN] = run;
}

__global__ __launch_bounds__(1024) void bhist_k() {
    __shared__ int h[NN];
    int t = threadIdx.x;
    for (int i = t; i < NN; i += 1024) h[i] = 0;
    __syncthreads();
    atomicAdd(&h[g_dst[blockIdx.x * EB + t]], 1);
    __syncthreads();
    for (int i = t; i < NN; i += 1024) g_bhist[blockIdx.x * NN + i] = h[i];
}

__global__ void colscan_k() {
    int n = blockIdx.x * 256 + threadIdx.x;
    if (n >= NN) return;
    int run = g_start[n];
#pragma unroll
    for (int b = 0; b < NB; b++) {
        int t = g_bhist[b * NN + n];
        g_bhist[b * NN + n] = run;
        run += t;
    }
}

__global__ __launch_bounds__(1024) void place_k() {
    __shared__ int d[EB];
    int t = threadIdx.x;
    int e = blockIdx.x * EB + t;
    d[t] = g_dst[e];
    __syncthreads();
    int myd = d[t];
    int rank = 0;
    for (int j = 0; j < EB; j++) {
        int v = d[j];
        if (j < t && v == myd) rank++;
    }
    g_perm[g_bhist[blockIdx.x * NN + myd] + rank] = e;
}

// ---------------- edge MLP layer 1 (all three convs); 128 thr/block ----------------
__global__ __launch_bounds__(128) void edge_mlp_k(
    const float* __restrict__ ea,
    const float* __restrict__ w1a, const float* __restrict__ b1a,
    const float* __restrict__ w2a, const float* __restrict__ b2a,
    const float* __restrict__ w3a, const float* __restrict__ b3a)
{
    __shared__ float sw[2448];
    for (int i = threadIdx.x; i < 2448; i += 128) {
        float v;
        if      (i < 512)  v = w1a[i];
        else if (i < 544)  v = b1a[i - 512];
        else if (i < 1312) v = w2a[i - 544];
        else if (i < 1360) v = b2a[i - 1312];
        else if (i < 2384) v = w3a[i - 1360];
        else               v = b3a[i - 2384];
        sw[i] = v;
    }
    __syncthreads();
    int e = blockIdx.x * 128 + threadIdx.x;
    float a[16];
    const float4* ep = (const float4*)(ea + (size_t)e * 16);
    float4 q0 = ep[0], q1 = ep[1], q2 = ep[2], q3 = ep[3];
    a[0]=q0.x; a[1]=q0.y; a[2]=q0.z; a[3]=q0.w;
    a[4]=q1.x; a[5]=q1.y; a[6]=q1.z; a[7]=q1.w;
    a[8]=q2.x; a[9]=q2.y; a[10]=q2.z; a[11]=q2.w;
    a[12]=q3.x; a[13]=q3.y; a[14]=q3.z; a[15]=q3.w;

    for (int j = 0; j < 32; j++) {
        float s = sw[512 + j];
#pragma unroll
        for (int i = 0; i < 16; i++) s = fmaf(a[i], sw[i * 32 + j], s);
        g_m[(size_t)j * NE + e] = lrelu(s);
    }
    g_m[(size_t)32 * NE + e] = 1.0f;

    for (int j = 0; j < 48; j++) {
        float s = sw[1312 + j];
#pragma unroll
        for (int i = 0; i < 16; i++) s = fmaf(a[i], sw[544 + i * 48 + j], s);
        g_m[(size_t)(33 + j) * NE + e] = lrelu(s);
    }
    g_m[(size_t)81 * NE + e] = 1.0f;

    for (int j = 0; j < 64; j++) {
        float s = sw[2384 + j];
#pragma unroll
        for (int i = 0; i < 16; i++) s = fmaf(a[i], sw[1360 + i * 64 + j], s);
        g_m[(size_t)(82 + j) * NE + e] = lrelu(s);
    }
    g_m[(size_t)146 * NE + e] = 1.0f;
}

// ---------------- Wcat = [wb | bias | root], tf32-split into g_Wh/g_Wl ----------------
__global__ void build_wcat_k(const float* __restrict__ wb, const float* __restrict__ bb,
                             const float* __restrict__ root, int inC, int K, int OUT)
{
    int idx = blockIdx.x * 256 + threadIdx.x;
    int Cc = (K + 2) * OUT;
    if (idx >= inC * Cc) return;
    int i = idx / Cc, c = idx - i * Cc;
    int k = c / OUT, o = c - k * OUT;
    float v;
    if (k < K)       v = wb[(size_t)k * inC * OUT + i * OUT + o];
    else if (k == K) v = bb[i * OUT + o];
    else             v = root[i * OUT + o];
    float h = tf32r(v);
    g_Wh[idx] = h;
    g_Wl[idx] = tf32r(v - h);
}

// ---------------- SGEMM (tf32 3-term, pre-split operands) ----------------
// block 128x64, 8 warps (4x2), warp tile 32x32, K-tile 16, mma m16n8k8
// c += ah*bh + ah*bl + al*bh   (al*bl ~2^-26 rel — dropped)
__global__ __launch_bounds__(256, 3) void sgemm_k(int Kd, int Cc)
{
    __shared__ float Ah[128][20], Al[128][20];   // [m][k], row stride 20 (16B-aligned)
    __shared__ float Bh[16][72],  Bl[16][72];    // [k][n], row stride 72 (16B-aligned)
    int tid = threadIdx.x;
    int lane = tid & 31, warp = tid >> 5;
    int warpM = warp >> 1, warpN = warp & 1;
    int brow = blockIdx.y * 128, bcol = blockIdx.x * 64;
    int g = lane >> 2, t = lane & 3;

    float c[2][4][4];
#pragma unroll
    for (int mt = 0; mt < 2; mt++)
#pragma unroll
        for (int nt = 0; nt < 4; nt++)
#pragma unroll
            for (int r = 0; r < 4; r++) c[mt][nt][r] = 0.f;

    for (int k0 = 0; k0 < Kd; k0 += 16) {
        // A tile 128x16 (float4 copies from pre-split globals)
#pragma unroll
        for (int i = 0; i < 2; i++) {
            int id = tid + i * 256;           // 0..511
            int row = id >> 2, kq = (id & 3) * 4;
            size_t off = (size_t)(brow + row) * Kd + k0 + kq;
            *(float4*)&Ah[row][kq] = *(const float4*)&g_Ah[off];
            *(float4*)&Al[row][kq] = *(const float4*)&g_Al[off];
        }
        // B tile 16x64 (guarded scalar)
        {
            int row = tid >> 4, c0 = (tid & 15) * 4;
            size_t base = (size_t)(k0 + row) * Cc + bcol + c0;
#pragma unroll
            for (int j = 0; j < 4; j++) {
                int col = bcol + c0 + j;
                bool ok = col < Cc;
                Bh[row][c0 + j] = ok ? g_Wh[base + j] : 0.f;
                Bl[row][c0 + j] = ok ? g_Wl[base + j] : 0.f;
            }
        }
        __syncthreads();
#pragma unroll
        for (int kk = 0; kk < 16; kk += 8) {
            unsigned ah[2][4], al[2][4];
#pragma unroll
            for (int mt = 0; mt < 2; mt++) {
                int r0 = warpM * 32 + mt * 16;
                ah[mt][0] = __float_as_uint(Ah[r0 + g][kk + t]);
                ah[mt][1] = __float_as_uint(Ah[r0 + g + 8][kk + t]);
                ah[mt][2] = __float_as_uint(Ah[r0 + g][kk + t + 4]);
                ah[mt][3] = __float_as_uint(Ah[r0 + g + 8][kk + t + 4]);
                al[mt][0] = __float_as_uint(Al[r0 + g][kk + t]);
                al[mt][1] = __float_as_uint(Al[r0 + g + 8][kk + t]);
                al[mt][2] = __float_as_uint(Al[r0 + g][kk + t + 4]);
                al[mt][3] = __float_as_uint(Al[r0 + g + 8][kk + t + 4]);
            }
#pragma unroll
            for (int nt = 0; nt < 4; nt++) {
                int n0 = warpN * 32 + nt * 8;
                unsigned bh[2], bl[2];
                bh[0] = __float_as_uint(Bh[kk + t][n0 + g]);
                bh[1] = __float_as_uint(Bh[kk + t + 4][n0 + g]);
                bl[0] = __float_as_uint(Bl[kk + t][n0 + g]);
                bl[1] = __float_as_uint(Bl[kk + t + 4][n0 + g]);
#pragma unroll
                for (int mt = 0; mt < 2; mt++) {
                    mma_tf32(c[mt][nt], ah[mt], bl);
                    mma_tf32(c[mt][nt], al[mt], bh);
                    mma_tf32(c[mt][nt], ah[mt], bh);
                }
            }
        }
        __syncthreads();
    }
#pragma unroll
    for (int mt = 0; mt < 2; mt++) {
#pragma unroll
        for (int nt = 0; nt < 4; nt++) {
            int row = brow + warpM * 32 + mt * 16 + g;
            int col = bcol + warpN * 32 + nt * 8 + 2 * t;
            if (col < Cc) {   // Cc even, col even -> col+1 < Cc too
                *(float2*)&g_Q[(size_t)row * Cc + col] =
                    make_float2(c[mt][nt][0], c[mt][nt][1]);
                *(float2*)&g_Q[(size_t)(row + 8) * Cc + col] =
                    make_float2(c[mt][nt][2], c[mt][nt][3]);
            }
        }
    }
}

// ---------------- per-edge message (32 threads/edge, float2) ----------------
__global__ __launch_bounds__(256) void edge_msg64_k(int Cc, int Kp1, int mOff)
{
    int t = blockIdx.x * 256 + threadIdx.x;   // NE*32 threads
    int e = t >> 5, lane = t & 31;
    int o = lane * 2;
    const float* mp = g_m + mOff + e;
    const float* q = g_Q + (size_t)g_src[e] * Cc + o;
    float a0 = 0.f, a1 = 0.f;
#pragma unroll 4
    for (int k = 0; k < Kp1; k++) {
        float mv = __ldg(mp + (size_t)k * NE);
        float2 qv = *(const float2*)(q + (size_t)k * 64);
        a0 = fmaf(mv, qv.x, a0);
        a1 = fmaf(mv, qv.y, a1);
    }
    *(float2*)&g_msg[(size_t)e * 64 + o] = make_float2(a0, a1);
}

__global__ __launch_bounds__(256) void edge_msg16_k(int Cc, int Kp1, int mOff)
{
    int t = blockIdx.x * 256 + threadIdx.x;
    int e = t >> 4, o = t & 15;
    const float* mp = g_m + mOff + e;
    const float* q = g_Q + (size_t)g_src[e] * Cc + o;
    float acc = 0.f;
#pragma unroll 4
    for (int k = 0; k < Kp1; k++)
        acc = fmaf(__ldg(mp + (size_t)k * NE), __ldg(q + (size_t)k * 16), acc);
    g_msg[t] = acc;
}

// -------- scatter-mean + root + bias + lrelu, fused tf32-split output (+concat x) ----
__global__ __launch_bounds__(256) void agg64_k(int Cc, int rootCol,
    const float* __restrict__ bias, const float* __restrict__ x)
{
    int gt = blockIdx.x * 256 + threadIdx.x;
    int node = gt >> 5, lane = gt & 31;
    int s = g_start[node], en = g_start[node + 1];
    float a0 = 0.f, a1 = 0.f;
    for (int j = s; j < en; j++) {
        int e = g_perm[j];
        const float* mr = g_msg + (size_t)e * 64;
        a0 += mr[lane];
        a1 += mr[lane + 32];
    }
    float cf = g_cntf[node];
    const float* qr = g_Q + (size_t)node * Cc + rootCol;
    float v0 = lrelu(a0 / cf + qr[lane] + bias[lane]);
    float v1 = lrelu(a1 / cf + qr[lane + 32] + bias[lane + 32]);
    float h0 = tf32r(v0);
    g_Ah[node * 80 + lane] = h0;
    g_Al[node * 80 + lane] = tf32r(v0 - h0);
    float h1 = tf32r(v1);
    g_Ah[node * 80 + lane + 32] = h1;
    g_Al[node * 80 + lane + 32] = tf32r(v1 - h1);
    if (lane < 16) {
        float xv = x[node * 16 + lane];
        float hx = tf32r(xv);
        g_Ah[node * 80 + 64 + lane] = hx;
        g_Al[node * 80 + 64 + lane] = tf32r(xv - hx);
    }
}

__global__ __launch_bounds__(256) void agg16_k(int Cc, int rootCol, const float* __restrict__ bias)
{
    int gt = blockIdx.x * 256 + threadIdx.x;
    int node = gt >> 4, lane = gt & 15;
    if (node >= NN) return;
    int s = g_start[node], en = g_start[node + 1];
    float a = 0.f;
    for (int j = s; j < en; j++)
        a += g_msg[(size_t)g_perm[j] * 16 + lane];
    g_d3[node * 16 + lane] =
        lrelu(a / g_cntf[node] + g_Q[(size_t)node * Cc + rootCol + lane] + bias[lane]);
}

// ---------------- JAX threefry2x32, PARTITIONABLE mode, bit_width=32 -----------
// bits[i] = out0 ^ out1 of threefry2x32((0,42), hi=0, lo=i)
__device__ __forceinline__ unsigned threefry_xor(unsigned x0, unsigned x1)
{
    const unsigned ks0 = 0u, ks1 = 42u, ks2 = 0u ^ 42u ^ 0x1BD11BDAu;
    unsigned v0 = x0 + ks0, v1 = x1 + ks1;
#define TFR(d) { v0 += v1; v1 = (v1 << d) | (v1 >> (32 - d)); v1 ^= v0; }
    TFR(13) TFR(15) TFR(26) TFR(6)   v0 += ks1; v1 += ks2 + 1u;
    TFR(17) TFR(29) TFR(16) TFR(24)  v0 += ks2; v1 += ks0 + 2u;
    TFR(13) TFR(15) TFR(26) TFR(6)   v0 += ks0; v1 += ks1 + 3u;
    TFR(17) TFR(29) TFR(16) TFR(24)  v0 += ks1; v1 += ks2 + 4u;
    TFR(13) TFR(15) TFR(26) TFR(6)   v0 += ks2; v1 += ks0 + 5u;
#undef TFR
    return v0 ^ v1;
}

__device__ __forceinline__ float bits_to_gumbel(unsigned b)
{
    float f = __uint_as_float((b >> 9) | 0x3F800000u) - 1.0f;  // [0,1)
    const float tiny = __uint_as_float(0x00800000u);           // FLT_MIN (normal)
    float u = fmaxf(f * 1.0f + tiny, tiny);
    return -logf(-logf(u));
}

__global__ void gumbel_k()
{
    int i = blockIdx.x * 256 + threadIdx.x;
    g_gum[i] = bits_to_gumbel(threefry_xor(0u, (unsigned)i));
}

// ---------------- final: one-hot(argmin(d3 + g)) ----------------
__global__ void out_k(float* __restrict__ out)
{
    int n = blockIdx.x * 256 + threadIdx.x;
    if (n >= NN) return;
    const float* d = g_d3 + n * 16;
    const float* g = g_gum + n * 16;
    float best = d[0] + g[0];
    int bi = 0;
#pragma unroll
    for (int c = 1; c < 16; c++) {
        float z = d[c] + g[c];
        if (z < best) { best = z; bi = c; }
    }
#pragma unroll
    for (int c = 0; c < 16; c++) out[n * 16 + c] = (c == bi) ? 1.0f : 0.0f;
}

// ---------------- host launch ----------------
extern "C" void kernel_launch(void* const* d_in, const int* in_sizes, int n_in,
                              void* d_out, int out_size)
{
    (void)in_sizes; (void)n_in; (void)out_size;
    const float* x     = (const float*)d_in[0];
    const void*  ei    = d_in[1];
    const float* ea    = (const float*)d_in[2];
    const float* w1a   = (const float*)d_in[3];
    const float* b1a   = (const float*)d_in[4];
    const float* w1b   = (const float*)d_in[5];
    const float* b1b   = (const float*)d_in[6];
    const float* root1 = (const float*)d_in[7];
    const float* bias1 = (const float*)d_in[8];
    const float* w2a   = (const float*)d_in[9];
    const float* b2a   = (const float*)d_in[10];
    const float* w2b   = (const float*)d_in[11];
    const float* b2b   = (const float*)d_in[12];
    const float* root2 = (const float*)d_in[13];
    const float* bias2 = (const float*)d_in[14];
    const float* w3a   = (const float*)d_in[15];
    const float* b3a   = (const float*)d_in[16];
    const float* w3b   = (const float*)d_in[17];
    const float* b3b   = (const float*)d_in[18];
    const float* root3 = (const float*)d_in[19];
    const float* bias3 = (const float*)d_in[20];
    float* out = (float*)d_out;

    // index 3 = ncu capture slot -> sgemm_k (conv1)
    detect_k<<<1, 32>>>(ei);
    split_x_k<<<NN * 16 / 256, 256>>>(x);
    build_wcat_k<<<(16 * 2176 + 255) / 256, 256>>>(w1b, b1b, root1, 16, 32, 64);
    sgemm_k<<<dim3(34, 64), 256>>>(16, 2176);           // conv1 Q  (profiled)
    convert_k<<<NE / 256, 256>>>(ei);
    edge_mlp_k<<<NE / 128, 128>>>(ea, w1a, b1a, w2a, b2a, w3a, b3a);
    edge_msg64_k<<<NE * 32 / 256, 256>>>(2176, 33, 0);

    // CSR build (needed before agg)
    zero_cnt_k<<<NN / 256, 256>>>();
    hist_k<<<NE / 256, 256>>>();
    scan_k<<<1, 1024>>>();
    bhist_k<<<NB, 1024>>>();
    colscan_k<<<NN / 256, 256>>>();
    place_k<<<NB, 1024>>>();
    gumbel_k<<<131072 / 256, 256>>>();

    agg64_k<<<NN * 32 / 256, 256>>>(2176, 33 * 64, bias1, x);   // writes split d1

    // conv2: in=80, K=48, OUT=64, Cc=50*64=3200
    build_wcat_k<<<(80 * 3200 + 255) / 256, 256>>>(w2b, b2b, root2, 80, 48, 64);
    sgemm_k<<<dim3(50, 64), 256>>>(80, 3200);
    edge_msg64_k<<<NE * 32 / 256, 256>>>(3200, 49, 33 * NE);
    agg64_k<<<NN * 32 / 256, 256>>>(3200, 49 * 64, bias2, x);   // writes split d2

    // conv3: in=80, K=64, OUT=16, Cc=66*16=1056
    build_wcat_k<<<(80 * 1056 + 255) / 256, 256>>>(w3b, b3b, root3, 80, 64, 16);
    sgemm_k<<<dim3(17, 64), 256>>>(80, 1056);
    edge_msg16_k<<<NE * 16 / 256, 256>>>(1056, 65, 82 * NE);
    agg16_k<<<NN * 16 / 256, 256>>>(1056, 65 * 16, bias3);

    out_k<<<NN / 256, 256>>>(out);
}

// round 12
// speedup vs baseline: 1.5906x; 1.5906x over previous
#include <cuda_runtime.h>

#define NN 8192
#define NE 32768
#define NB 32
#define EB 1024
#define RR 8

// ---------------- device scratch (no allocations allowed) ----------------
__device__ int   g_is64;
__device__ int   g_src[NE], g_dst[NE];
__device__ int   g_cnt[NN];
__device__ int   g_start[NN + 1];
__device__ float g_cntf[NN];
__device__ int   g_bhist[NB * NN];
__device__ int   g_perm[NE];
__device__ float g_m[147 * NE];            // m1_aug(33)|m2_aug(49)|m3_aug(65), column-major [k][e]
__device__ float g_Wh[80 * 3200];          // Wcat tf32-hi for current conv
__device__ float g_Wl[80 * 3200];          // Wcat tf32-lo
__device__ float g_Ah[NN * 80];            // A (node features) tf32-hi for current conv
__device__ float g_Al[NN * 80];            // A tf32-lo
__device__ float g_Q[(size_t)NN * 3200];   // Q = A @ Wcat (max ~105 MB)
__device__ float g_msg[NE * 64];
__device__ float g_d3[NN * 16];
__device__ float g_gum[NN * 16];

__device__ __forceinline__ float lrelu(float v) { return v >= 0.f ? v : 0.01f * v; }

// ---------------- tf32 helpers ----------------
__device__ __forceinline__ float tf32r(float a) {
    unsigned u;
    asm("cvt.rna.tf32.f32 %0, %1;" : "=r"(u) : "f"(a));
    return __uint_as_float(u);
}

__device__ __forceinline__ void mma_tf32(float* c, const unsigned* a, const unsigned* b) {
    asm("mma.sync.aligned.m16n8k8.row.col.f32.tf32.tf32.f32 "
        "{%0,%1,%2,%3}, {%4,%5,%6,%7}, {%8,%9}, {%0,%1,%2,%3};"
        : "+f"(c[0]), "+f"(c[1]), "+f"(c[2]), "+f"(c[3])
        : "r"(a[0]), "r"(a[1]), "r"(a[2]), "r"(a[3]), "r"(b[0]), "r"(b[1]));
}

// ---------------- edge_index dtype detection + conversion ----------------
__global__ void detect_k(const void* ei) {
    if (threadIdx.x == 0) {
        const long long* p = (const long long*)ei;
        int ok = 1;
        for (int i = 0; i < 64; i++) {
            long long v = p[i];
            if (v < 0 || v >= NN) ok = 0;
        }
        g_is64 = ok;
    }
}

__global__ void convert_k(const void* ei) {
    int e = blockIdx.x * 256 + threadIdx.x;
    if (e >= NE) return;
    if (g_is64) {
        const long long* p = (const long long*)ei;
        g_src[e] = (int)p[e];
        g_dst[e] = (int)p[NE + e];
    } else {
        const int* p = (const int*)ei;
        g_src[e] = p[e];
        g_dst[e] = p[NE + e];
    }
}

// ---------------- conv1 A split: x[8192*16] -> g_Ah/g_Al ----------------
__global__ void split_x_k(const float* __restrict__ x) {
    int i = blockIdx.x * 256 + threadIdx.x;   // NN*16
    float v = x[i];
    float h = tf32r(v);
    g_Ah[i] = h;
    g_Al[i] = tf32r(v - h);
}

// ---------------- deterministic dst-CSR build ----------------
__global__ void zero_cnt_k() { g_cnt[blockIdx.x * 256 + threadIdx.x] = 0; }

__global__ void hist_k() {
    int e = blockIdx.x * 256 + threadIdx.x;
    atomicAdd(&g_cnt[g_dst[e]], 1);
}

__global__ __launch_bounds__(1024) void scan_k() {
    __shared__ int ps[1024];
    int t = threadIdx.x;
    int loc[8];
    int s = 0;
    for (int i = 0; i < 8; i++) { loc[i] = g_cnt[t * 8 + i]; s += loc[i]; }
    ps[t] = s;
    __syncthreads();
    for (int d = 1; d < 1024; d <<= 1) {
        int v = (t >= d) ? ps[t - d] : 0;
        __syncthreads();
        ps[t] += v;
        __syncthreads();
    }
    int run = (t > 0) ? ps[t - 1] : 0;
    for (int i = 0; i < 8; i++) {
        int n = t * 8 + i;
        g_start[n] = run;
        g_cntf[n]  = (float)(loc[i] > 1 ? loc[i] : 1);
        run += loc[i];
    }
    if (t == 1023) g_start[NN] = run;
}

__global__ __launch_bounds__(1024) void bhist_k() {
    __shared__ int h[NN];
    int t = threadIdx.x;
    for (int i = t; i < NN; i += 1024) h[i] = 0;
    __syncthreads();
    atomicAdd(&h[g_dst[blockIdx.x * EB + t]], 1);
    __syncthreads();
    for (int i = t; i < NN; i += 1024) g_bhist[blockIdx.x * NN + i] = h[i];
}

__global__ void colscan_k() {
    int n = blockIdx.x * 256 + threadIdx.x;
    if (n >= NN) return;
    int run = g_start[n];
#pragma unroll
    for (int b = 0; b < NB; b++) {
        int t = g_bhist[b * NN + n];
        g_bhist[b * NN + n] = run;
        run += t;
    }
}

__global__ __launch_bounds__(1024) void place_k() {
    __shared__ int d[EB];
    int t = threadIdx.x;
    int e = blockIdx.x * EB + t;
    d[t] = g_dst[e];
    __syncthreads();
    int myd = d[t];
    int rank = 0;
    for (int j = 0; j < EB; j++) {
        int v = d[j];
        if (j < t && v == myd) rank++;
    }
    g_perm[g_bhist[blockIdx.x * NN + myd] + rank] = e;
}

// ---------------- edge MLP layer 1 (all three convs); 128 thr/block ----------------
__global__ __launch_bounds__(128) void edge_mlp_k(
    const float* __restrict__ ea,
    const float* __restrict__ w1a, const float* __restrict__ b1a,
    const float* __restrict__ w2a, const float* __restrict__ b2a,
    const float* __restrict__ w3a, const float* __restrict__ b3a)
{
    __shared__ float sw[2448];
    for (int i = threadIdx.x; i < 2448; i += 128) {
        float v;
        if      (i < 512)  v = w1a[i];
        else if (i < 544)  v = b1a[i - 512];
        else if (i < 1312) v = w2a[i - 544];
        else if (i < 1360) v = b2a[i - 1312];
        else if (i < 2384) v = w3a[i - 1360];
        else               v = b3a[i - 2384];
        sw[i] = v;
    }
    __syncthreads();
    int e = blockIdx.x * 128 + threadIdx.x;
    float a[16];
    const float4* ep = (const float4*)(ea + (size_t)e * 16);
    float4 q0 = ep[0], q1 = ep[1], q2 = ep[2], q3 = ep[3];
    a[0]=q0.x; a[1]=q0.y; a[2]=q0.z; a[3]=q0.w;
    a[4]=q1.x; a[5]=q1.y; a[6]=q1.z; a[7]=q1.w;
    a[8]=q2.x; a[9]=q2.y; a[10]=q2.z; a[11]=q2.w;
    a[12]=q3.x; a[13]=q3.y; a[14]=q3.z; a[15]=q3.w;

    for (int j = 0; j < 32; j++) {
        float s = sw[512 + j];
#pragma unroll
        for (int i = 0; i < 16; i++) s = fmaf(a[i], sw[i * 32 + j], s);
        g_m[(size_t)j * NE + e] = lrelu(s);
    }
    g_m[(size_t)32 * NE + e] = 1.0f;

    for (int j = 0; j < 48; j++) {
        float s = sw[1312 + j];
#pragma unroll
        for (int i = 0; i < 16; i++) s = fmaf(a[i], sw[544 + i * 48 + j], s);
        g_m[(size_t)(33 + j) * NE + e] = lrelu(s);
    }
    g_m[(size_t)81 * NE + e] = 1.0f;

    for (int j = 0; j < 64; j++) {
        float s = sw[2384 + j];
#pragma unroll
        for (int i = 0; i < 16; i++) s = fmaf(a[i], sw[1360 + i * 64 + j], s);
        g_m[(size_t)(82 + j) * NE + e] = lrelu(s);
    }
    g_m[(size_t)146 * NE + e] = 1.0f;
}

// ---------------- Wcat = [wb | bias | root], tf32-split into g_Wh/g_Wl ----------------
__global__ void build_wcat_k(const float* __restrict__ wb, const float* __restrict__ bb,
                             const float* __restrict__ root, int inC, int K, int OUT)
{
    int idx = blockIdx.x * 256 + threadIdx.x;
    int Cc = (K + 2) * OUT;
    if (idx >= inC * Cc) return;
    int i = idx / Cc, c = idx - i * Cc;
    int k = c / OUT, o = c - k * OUT;
    float v;
    if (k < K)       v = wb[(size_t)k * inC * OUT + i * OUT + o];
    else if (k == K) v = bb[i * OUT + o];
    else             v = root[i * OUT + o];
    float h = tf32r(v);
    g_Wh[idx] = h;
    g_Wl[idx] = tf32r(v - h);
}

// ---------------- A-tile global->regs / regs->smem helpers ----------------
__device__ __forceinline__ void lda_regs(int rt, int kt, int Kd, int tid,
                                         float4* h, float4* l)
{
#pragma unroll
    for (int s = 0; s < 2; s++) {
        int f = tid * 2 + s;
        int row = f >> 2, kq = (f & 3) * 4;
        size_t go = (size_t)(rt * 128 + row) * Kd + kt * 16 + kq;
        h[s] = *(const float4*)&g_Ah[go];
        l[s] = *(const float4*)&g_Al[go];
    }
}
__device__ __forceinline__ void sta_smem(float* Ab, int tid,
                                         const float4* h, const float4* l)
{
#pragma unroll
    for (int s = 0; s < 2; s++) {
        int f = tid * 2 + s;
        int row = f >> 2, kq = (f & 3) * 4;
        *(float4*)&Ab[row * 20 + kq] = h[s];
        *(float4*)&Ab[2560 + row * 20 + kq] = l[s];
    }
}

// ---------------- SGEMM (tf32 3-term, persistent rows, double-buffered A) --------
// grid (ceil(Cc/64), 8). Block: caches ALL B k-tiles, loops RR=8 row-tiles of 128.
// smem: B: KTn * (Bh[16][72] | Bl[16][72]) = KTn*2304 floats; A: 2 bufs of 5120.
// c += ah*bh + ah*bl + al*bh per (kk, nt, mt) — order identical to prior rounds.
__global__ __launch_bounds__(256, 2) void sgemm_k(int Kd, int Cc)
{
    extern __shared__ float sm[];
    const int KTn = Kd >> 4;
    float* Bsm = sm;                      // [kt][hi 16*72 | lo 16*72]
    float* Asm = sm + KTn * 2304;         // [2][hi 128*20 | lo 128*20]
    int tid = threadIdx.x;
    int lane = tid & 31, warp = tid >> 5;
    int warpM = warp >> 1, warpN = warp & 1;
    int bcol = blockIdx.x * 64;
    int rt0 = blockIdx.y * RR;
    int g = lane >> 2, t = lane & 3;

    // ---- load ALL B k-tiles (once per block) ----
    for (int i = tid; i < KTn * 1024; i += 256) {
        int kt = i >> 10, rem = i & 1023;
        int kr = rem >> 6, col = rem & 63;
        int gcol = bcol + col;
        float vh = 0.f, vl = 0.f;
        if (gcol < Cc) {
            size_t go = (size_t)(kt * 16 + kr) * Cc + gcol;
            vh = g_Wh[go]; vl = g_Wl[go];
        }
        float* bk = Bsm + kt * 2304;
        bk[kr * 72 + col] = vh;
        bk[1152 + kr * 72 + col] = vl;
    }
    // ---- preload A tile (rr=0, kt=0) into buffer 0 ----
    {
        float4 h[2], l[2];
        lda_regs(rt0, 0, Kd, tid, h, l);
        sta_smem(Asm, tid, h, l);
    }
    __syncthreads();

    float c[2][4][4];
#pragma unroll
    for (int mt = 0; mt < 2; mt++)
#pragma unroll
        for (int nt = 0; nt < 4; nt++)
#pragma unroll
            for (int r = 0; r < 4; r++) c[mt][nt][r] = 0.f;

    int total = RR * KTn;
    int kt = 0, rr = 0;
    for (int it = 0; it < total; it++) {
        int ktn = kt + 1, rrn = rr;
        if (ktn == KTn) { ktn = 0; rrn = rr + 1; }
        bool nx = (it + 1 < total);
        float4 nh[2], nl[2];
        if (nx) lda_regs(rt0 + rrn, ktn, Kd, tid, nh, nl);

        const float* Ab = Asm + (it & 1) * 5120;
        const float* Bk = Bsm + kt * 2304;
#pragma unroll
        for (int kk = 0; kk < 16; kk += 8) {
            unsigned ah[2][4], al[2][4];
#pragma unroll
            for (int mt = 0; mt < 2; mt++) {
                int r0 = warpM * 32 + mt * 16;
                ah[mt][0] = __float_as_uint(Ab[(r0 + g) * 20 + kk + t]);
                ah[mt][1] = __float_as_uint(Ab[(r0 + g + 8) * 20 + kk + t]);
                ah[mt][2] = __float_as_uint(Ab[(r0 + g) * 20 + kk + t + 4]);
                ah[mt][3] = __float_as_uint(Ab[(r0 + g + 8) * 20 + kk + t + 4]);
                al[mt][0] = __float_as_uint(Ab[2560 + (r0 + g) * 20 + kk + t]);
                al[mt][1] = __float_as_uint(Ab[2560 + (r0 + g + 8) * 20 + kk + t]);
                al[mt][2] = __float_as_uint(Ab[2560 + (r0 + g) * 20 + kk + t + 4]);
                al[mt][3] = __float_as_uint(Ab[2560 + (r0 + g + 8) * 20 + kk + t + 4]);
            }
#pragma unroll
            for (int nt = 0; nt < 4; nt++) {
                int n0 = warpN * 32 + nt * 8;
                unsigned bh[2], bl[2];
                bh[0] = __float_as_uint(Bk[(kk + t) * 72 + n0 + g]);
                bh[1] = __float_as_uint(Bk[(kk + t + 4) * 72 + n0 + g]);
                bl[0] = __float_as_uint(Bk[1152 + (kk + t) * 72 + n0 + g]);
                bl[1] = __float_as_uint(Bk[1152 + (kk + t + 4) * 72 + n0 + g]);
#pragma unroll
                for (int mt = 0; mt < 2; mt++) {
                    mma_tf32(c[mt][nt], ah[mt], bl);
                    mma_tf32(c[mt][nt], al[mt], bh);
                    mma_tf32(c[mt][nt], ah[mt], bh);
                }
            }
        }
        if (nx) sta_smem(Asm + ((it + 1) & 1) * 5120, tid, nh, nl);
        __syncthreads();

        if (kt == KTn - 1) {
            int brow = (rt0 + rr) * 128;
#pragma unroll
            for (int mt = 0; mt < 2; mt++) {
#pragma unroll
                for (int nt = 0; nt < 4; nt++) {
                    int row = brow + warpM * 32 + mt * 16 + g;
                    int col = bcol + warpN * 32 + nt * 8 + 2 * t;
                    if (col < Cc) {
                        *(float2*)&g_Q[(size_t)row * Cc + col] =
                            make_float2(c[mt][nt][0], c[mt][nt][1]);
                        *(float2*)&g_Q[(size_t)(row + 8) * Cc + col] =
                            make_float2(c[mt][nt][2], c[mt][nt][3]);
                    }
                    c[mt][nt][0] = 0.f; c[mt][nt][1] = 0.f;
                    c[mt][nt][2] = 0.f; c[mt][nt][3] = 0.f;
                }
            }
        }
        kt = ktn; rr = rrn;
    }
}

// ---------------- per-edge message (32 threads/edge, float2) ----------------
__global__ __launch_bounds__(256) void edge_msg64_k(int Cc, int Kp1, int mOff)
{
    int t = blockIdx.x * 256 + threadIdx.x;   // NE*32 threads
    int e = t >> 5, lane = t & 31;
    int o = lane * 2;
    const float* mp = g_m + mOff + e;
    const float* q = g_Q + (size_t)g_src[e] * Cc + o;
    float a0 = 0.f, a1 = 0.f;
#pragma unroll 4
    for (int k = 0; k < Kp1; k++) {
        float mv = __ldg(mp + (size_t)k * NE);
        float2 qv = *(const float2*)(q + (size_t)k * 64);
        a0 = fmaf(mv, qv.x, a0);
        a1 = fmaf(mv, qv.y, a1);
    }
    *(float2*)&g_msg[(size_t)e * 64 + o] = make_float2(a0, a1);
}

__global__ __launch_bounds__(256) void edge_msg16_k(int Cc, int Kp1, int mOff)
{
    int t = blockIdx.x * 256 + threadIdx.x;
    int e = t >> 4, o = t & 15;
    const float* mp = g_m + mOff + e;
    const float* q = g_Q + (size_t)g_src[e] * Cc + o;
    float acc = 0.f;
#pragma unroll 4
    for (int k = 0; k < Kp1; k++)
        acc = fmaf(__ldg(mp + (size_t)k * NE), __ldg(q + (size_t)k * 16), acc);
    g_msg[t] = acc;
}

// -------- scatter-mean + root + bias + lrelu, fused tf32-split output (+concat x) ----
__global__ __launch_bounds__(256) void agg64_k(int Cc, int rootCol,
    const float* __restrict__ bias, const float* __restrict__ x)
{
    int gt = blockIdx.x * 256 + threadIdx.x;
    int node = gt >> 5, lane = gt & 31;
    int s = g_start[node], en = g_start[node + 1];
    float a0 = 0.f, a1 = 0.f;
    for (int j = s; j < en; j++) {
        int e = g_perm[j];
        const float* mr = g_msg + (size_t)e * 64;
        a0 += mr[lane];
        a1 += mr[lane + 32];
    }
    float cf = g_cntf[node];
    const float* qr = g_Q + (size_t)node * Cc + rootCol;
    float v0 = lrelu(a0 / cf + qr[lane] + bias[lane]);
    float v1 = lrelu(a1 / cf + qr[lane + 32] + bias[lane + 32]);
    float h0 = tf32r(v0);
    g_Ah[node * 80 + lane] = h0;
    g_Al[node * 80 + lane] = tf32r(v0 - h0);
    float h1 = tf32r(v1);
    g_Ah[node * 80 + lane + 32] = h1;
    g_Al[node * 80 + lane + 32] = tf32r(v1 - h1);
    if (lane < 16) {
        float xv = x[node * 16 + lane];
        float hx = tf32r(xv);
        g_Ah[node * 80 + 64 + lane] = hx;
        g_Al[node * 80 + 64 + lane] = tf32r(xv - hx);
    }
}

__global__ __launch_bounds__(256) void agg16_k(int Cc, int rootCol, const float* __restrict__ bias)
{
    int gt = blockIdx.x * 256 + threadIdx.x;
    int node = gt >> 4, lane = gt & 15;
    if (node >= NN) return;
    int s = g_start[node], en = g_start[node + 1];
    float a = 0.f;
    for (int j = s; j < en; j++)
        a += g_msg[(size_t)g_perm[j] * 16 + lane];
    g_d3[node * 16 + lane] =
        lrelu(a / g_cntf[node] + g_Q[(size_t)node * Cc + rootCol + lane] + bias[lane]);
}

// ---------------- JAX threefry2x32, PARTITIONABLE mode, bit_width=32 -----------
// bits[i] = out0 ^ out1 of threefry2x32((0,42), hi=0, lo=i)
__device__ __forceinline__ unsigned threefry_xor(unsigned x0, unsigned x1)
{
    const unsigned ks0 = 0u, ks1 = 42u, ks2 = 0u ^ 42u ^ 0x1BD11BDAu;
    unsigned v0 = x0 + ks0, v1 = x1 + ks1;
#define TFR(d) { v0 += v1; v1 = (v1 << d) | (v1 >> (32 - d)); v1 ^= v0; }
    TFR(13) TFR(15) TFR(26) TFR(6)   v0 += ks1; v1 += ks2 + 1u;
    TFR(17) TFR(29) TFR(16) TFR(24)  v0 += ks2; v1 += ks0 + 2u;
    TFR(13) TFR(15) TFR(26) TFR(6)   v0 += ks0; v1 += ks1 + 3u;
    TFR(17) TFR(29) TFR(16) TFR(24)  v0 += ks1; v1 += ks2 + 4u;
    TFR(13) TFR(15) TFR(26) TFR(6)   v0 += ks2; v1 += ks0 + 5u;
#undef TFR
    return v0 ^ v1;
}

__device__ __forceinline__ float bits_to_gumbel(unsigned b)
{
    float f = __uint_as_float((b >> 9) | 0x3F800000u) - 1.0f;  // [0,1)
    const float tiny = __uint_as_float(0x00800000u);           // FLT_MIN (normal)
    float u = fmaxf(f * 1.0f + tiny, tiny);
    return -logf(-logf(u));
}

__global__ void gumbel_k()
{
    int i = blockIdx.x * 256 + threadIdx.x;
    g_gum[i] = bits_to_gumbel(threefry_xor(0u, (unsigned)i));
}

// ---------------- final: one-hot(argmin(d3 + g)) ----------------
__global__ void out_k(float* __restrict__ out)
{
    int n = blockIdx.x * 256 + threadIdx.x;
    if (n >= NN) return;
    const float* d = g_d3 + n * 16;
    const float* g = g_gum + n * 16;
    float best = d[0] + g[0];
    int bi = 0;
#pragma unroll
    for (int c = 1; c < 16; c++) {
        float z = d[c] + g[c];
        if (z < best) { best = z; bi = c; }
    }
#pragma unroll
    for (int c = 0; c < 16; c++) out[n * 16 + c] = (c == bi) ? 1.0f : 0.0f;
}

// ---------------- host launch ----------------
extern "C" void kernel_launch(void* const* d_in, const int* in_sizes, int n_in,
                              void* d_out, int out_size)
{
    (void)in_sizes; (void)n_in; (void)out_size;
    const float* x     = (const float*)d_in[0];
    const void*  ei    = d_in[1];
    const float* ea    = (const float*)d_in[2];
    const float* w1a   = (const float*)d_in[3];
    const float* b1a   = (const float*)d_in[4];
    const float* w1b   = (const float*)d_in[5];
    const float* b1b   = (const float*)d_in[6];
    const float* root1 = (const float*)d_in[7];
    const float* bias1 = (const float*)d_in[8];
    const float* w2a   = (const float*)d_in[9];
    const float* b2a   = (const float*)d_in[10];
    const float* w2b   = (const float*)d_in[11];
    const float* b2b   = (const float*)d_in[12];
    const float* root2 = (const float*)d_in[13];
    const float* bias2 = (const float*)d_in[14];
    const float* w3a   = (const float*)d_in[15];
    const float* b3a   = (const float*)d_in[16];
    const float* w3b   = (const float*)d_in[17];
    const float* b3b   = (const float*)d_in[18];
    const float* root3 = (const float*)d_in[19];
    const float* bias3 = (const float*)d_in[20];
    float* out = (float*)d_out;

    cudaFuncSetAttribute(sgemm_k, cudaFuncAttributeMaxDynamicSharedMemorySize, 87040);

    // index 3 = ncu capture slot -> sgemm_k (conv1)
    detect_k<<<1, 32>>>(ei);
    split_x_k<<<NN * 16 / 256, 256>>>(x);
    build_wcat_k<<<(16 * 2176 + 255) / 256, 256>>>(w1b, b1b, root1, 16, 32, 64);
    sgemm_k<<<dim3(34, 8), 256, (1 * 2304 + 2 * 5120) * 4>>>(16, 2176);   // conv1 (profiled)
    convert_k<<<NE / 256, 256>>>(ei);
    edge_mlp_k<<<NE / 128, 128>>>(ea, w1a, b1a, w2a, b2a, w3a, b3a);
    edge_msg64_k<<<NE * 32 / 256, 256>>>(2176, 33, 0);

    // CSR build (needed before agg)
    zero_cnt_k<<<NN / 256, 256>>>();
    hist_k<<<NE / 256, 256>>>();
    scan_k<<<1, 1024>>>();
    bhist_k<<<NB, 1024>>>();
    colscan_k<<<NN / 256, 256>>>();
    place_k<<<NB, 1024>>>();
    gumbel_k<<<131072 / 256, 256>>>();

    agg64_k<<<NN * 32 / 256, 256>>>(2176, 33 * 64, bias1, x);   // writes split d1

    // conv2: in=80, K=48, OUT=64, Cc=50*64=3200
    build_wcat_k<<<(80 * 3200 + 255) / 256, 256>>>(w2b, b2b, root2, 80, 48, 64);
    sgemm_k<<<dim3(50, 8), 256, (5 * 2304 + 2 * 5120) * 4>>>(80, 3200);
    edge_msg64_k<<<NE * 32 / 256, 256>>>(3200, 49, 33 * NE);
    agg64_k<<<NN * 32 / 256, 256>>>(3200, 49 * 64, bias2, x);   // writes split d2

    // conv3: in=80, K=64, OUT=16, Cc=66*16=1056
    build_wcat_k<<<(80 * 1056 + 255) / 256, 256>>>(w3b, b3b, root3, 80, 64, 16);
    sgemm_k<<<dim3(17, 8), 256, (5 * 2304 + 2 * 5120) * 4>>>(80, 1056);
    edge_msg16_k<<<NE * 16 / 256, 256>>>(1056, 65, 82 * NE);
    agg16_k<<<NN * 16 / 256, 256>>>(1056, 65 * 16, bias3);

    out_k<<<NN / 256, 256>>>(out);
}